// round 1
// baseline (speedup 1.0000x reference)
#include <cuda_runtime.h>
#include <cuda_bf16.h>
#include <math.h>

#define NN 768
#define NJ 17
#define NPAIR (NN * NN)          // 589824
#define TILE_J 96                // j-tile per block
#define WARPS_PER_BLOCK 8

// -------- device scratch (no allocations allowed) --------
__device__ float g_vf[NN * 128];     // relu(vis_maps @ W_vis)
__device__ float g_T1[NJ * 128];     // relu(W_cls_u)
__device__ float g_T2[NJ * 128];     // relu(W_cls_v)
__device__ float g_WL[2 * 128];      // combined W_loc (ch0+ch2, ch1+ch3)
__device__ float g_nx[NN];           // x / 48
__device__ float g_ny[NN];           // y / 64

// ---------------- prep kernels ----------------
__global__ void prep_small(const float* __restrict__ loc,
                           const float* __restrict__ Wcu,
                           const float* __restrict__ Wcv,
                           const float* __restrict__ Wloc) {
    int t = threadIdx.x;  // 256 threads
    for (int idx = t; idx < NJ * 128; idx += 256) {
        g_T1[idx] = fmaxf(Wcu[idx], 0.0f);
        g_T2[idx] = fmaxf(Wcv[idx], 0.0f);
    }
    for (int c = t; c < 128; c += 256) {
        g_WL[c]       = Wloc[c]         + Wloc[2 * 128 + c];
        g_WL[128 + c] = Wloc[128 + c]   + Wloc[3 * 128 + c];
    }
    for (int i = t; i < NN; i += 256) {
        g_nx[i] = loc[i * 5 + 3] * (1.0f / 48.0f);
        g_ny[i] = loc[i * 5 + 4] * (1.0f / 64.0f);
    }
}

__global__ void prep_vf(const float* __restrict__ vm,
                        const float* __restrict__ Wvis) {
    __shared__ float sv[32];
    int i = blockIdx.x;
    int c = threadIdx.x;  // 128 threads
    if (c < 32) sv[c] = vm[i * 32 + c];
    __syncthreads();
    float acc = 0.0f;
#pragma unroll
    for (int k = 0; k < 32; k++)
        acc = fmaf(sv[k], Wvis[k * 128 + c], acc);
    g_vf[i * 128 + c] = fmaxf(acc, 0.0f);
}

// ---------------- main kernel ----------------
__device__ __forceinline__ float4 mul4(float4 a, float4 b) {
    return make_float4(a.x * b.x, a.y * b.y, a.z * b.z, a.w * b.w);
}
__device__ __forceinline__ float dot4(float4 a, float4 b) {
    return fmaf(a.x, b.x, fmaf(a.y, b.y, fmaf(a.z, b.z, a.w * b.w)));
}

__global__ void __launch_bounds__(WARPS_PER_BLOCK * 32)
assoc_main(const int* __restrict__ cls,
           const float* __restrict__ Wp,
           float* __restrict__ out) {
    __shared__ float sT2[NJ * 128];
    for (int idx = threadIdx.x; idx < NJ * 128; idx += WARPS_PER_BLOCK * 32)
        sT2[idx] = g_T2[idx];
    __syncthreads();

    const int warp = threadIdx.x >> 5;
    const int lane = threadIdx.x & 31;
    const int c4 = lane * 4;

    const int i  = blockIdx.x * WARPS_PER_BLOCK + warp;  // row (0..767)
    const int j0 = blockIdx.y * TILE_J;

    // i-invariant registers
    const float4 vi  = *reinterpret_cast<const float4*>(&g_vf[i * 128 + c4]);
    const int    ci  = cls[i];
    const float4 f1  = *reinterpret_cast<const float4*>(&g_T1[ci * 128 + c4]);
    const float4 wpv = *reinterpret_cast<const float4*>(&Wp[c4]);
    const float4 wpc = *reinterpret_cast<const float4*>(&Wp[128 + c4]);
    const float4 wpg = *reinterpret_cast<const float4*>(&Wp[256 + c4]);
    const float4 wl0 = *reinterpret_cast<const float4*>(&g_WL[c4]);
    const float4 wl1 = *reinterpret_cast<const float4*>(&g_WL[128 + c4]);
    const float  nxi = g_nx[i];
    const float  nyi = g_ny[i];

    float* __restrict__ ass  = out;                       // [N, N]
    float* __restrict__ feat = out + (size_t)NPAIR;       // [N, N, 384]
    float* frow = feat + ((size_t)i * NN + j0) * 384;

#pragma unroll 2
    for (int jj = 0; jj < TILE_J; jj++) {
        const int j = j0 + jj;
        const float4 vj = *reinterpret_cast<const float4*>(&g_vf[j * 128 + c4]);
        const int    cj = cls[j];
        const float4 f2 = *reinterpret_cast<const float4*>(&sT2[cj * 128 + c4]);
        const float dx = nxi - g_nx[j];
        const float dy = nyi - g_ny[j];
        const float g0 = dx * dx;
        const float g1 = dy * dy;

        // channel values
        const float4 v  = mul4(vi, vj);
        const float4 cl = mul4(f1, f2);
        float4 ge;
        ge.x = fmaxf(fmaf(g0, wl0.x, g1 * wl1.x), 0.0f);
        ge.y = fmaxf(fmaf(g0, wl0.y, g1 * wl1.y), 0.0f);
        ge.z = fmaxf(fmaf(g0, wl0.z, g1 * wl1.z), 0.0f);
        ge.w = fmaxf(fmaf(g0, wl0.w, g1 * wl1.w), 0.0f);

        float* p = frow + (size_t)jj * 384;
        *reinterpret_cast<float4*>(p + c4)        = v;
        *reinterpret_cast<float4*>(p + 128 + c4)  = cl;
        *reinterpret_cast<float4*>(p + 256 + c4)  = ge;

        // logit reduction
        float acc = dot4(v, wpv) + dot4(cl, wpc) + dot4(ge, wpg);
#pragma unroll
        for (int off = 16; off; off >>= 1)
            acc += __shfl_xor_sync(0xFFFFFFFFu, acc, off);
        if (lane == 0)
            ass[(size_t)i * NN + j] = 1.0f / (1.0f + __expf(-acc));
    }
}

// ---------------- launch ----------------
extern "C" void kernel_launch(void* const* d_in, const int* in_sizes, int n_in,
                              void* d_out, int out_size) {
    const float* vis_maps = (const float*)d_in[0];   // [768, 32]
    const float* locations = (const float*)d_in[1];  // [768, 5]
    const int*   kpt_cls   = (const int*)d_in[2];    // [768]
    const float* W_cls_u   = (const float*)d_in[3];  // [17, 128]
    const float* W_cls_v   = (const float*)d_in[4];  // [17, 128]
    const float* W_loc     = (const float*)d_in[5];  // [4, 128]
    const float* W_vis     = (const float*)d_in[6];  // [32, 128]
    const float* W_pred    = (const float*)d_in[7];  // [384, 1]
    float* out = (float*)d_out;

    prep_small<<<1, 256>>>(locations, W_cls_u, W_cls_v, W_loc);
    prep_vf<<<NN, 128>>>(vis_maps, W_vis);

    dim3 grid(NN / WARPS_PER_BLOCK, NN / TILE_J);  // (96, 8)
    assoc_main<<<grid, WARPS_PER_BLOCK * 32>>>(kpt_cls, W_pred, out);
}